// round 1
// baseline (speedup 1.0000x reference)
#include <cuda_runtime.h>

// Problem constants
#define T_TOK 8192
#define NJ    24      // joints
#define DIM   256     // per-joint feature dim
#define NH    8       // heads
#define FD    32      // head dim
#define ND    6144    // NJ*DIM (token row width)
#define HF    256     // NH*FD

// Scratch: Q/K/V in [t][h][n][f] layout (fp32), 201 MB each.
__device__ float g_Q[(size_t)T_TOK * NH * NJ * FD];
__device__ float g_K[(size_t)T_TOK * NH * NJ * FD];
__device__ float g_V[(size_t)T_TOK * NH * NJ * FD];

// ---------------------------------------------------------------------------
// Kernel 1: QKV projections.
// For joint n:  A_n[t][d] = x[t, n*256 + d]   (row stride ND)
//   K/V: B[d][c=h*32+f] = Wk[h][d][f]   (shared across joints)
//   Q:   B[d][c]        = Wq[h][n][d][f]
// C[t][c] -> g_{Q,K,V}[((t*8+h)*24+n)*32+f]
// Tiling: BM=64 tokens, BN=64 cols, BK=32, 256 threads, 4x4 per-thread tile.
// ---------------------------------------------------------------------------
#define BM 64
#define BN 64
#define BK 32

__global__ __launch_bounds__(256)
void qkv_gemm(const float* __restrict__ x,
              const float* __restrict__ Wq, const float* __restrict__ bq,
              const float* __restrict__ Wk, const float* __restrict__ bk,
              const float* __restrict__ Wv, const float* __restrict__ bv)
{
    __shared__ float As[BK][BM + 1];  // transposed A tile, padded
    __shared__ float Bs[BK][BN];

    const int n     = blockIdx.z / 3;
    const int which = blockIdx.z % 3;   // 0=Q 1=K 2=V
    const int t0    = blockIdx.x * BM;
    const int c0    = blockIdx.y * BN;
    const int tid   = threadIdx.x;

    const float* W;
    const float* bias;
    if (which == 0)      { W = Wq; bias = bq; }
    else if (which == 1) { W = Wk; bias = bk; }
    else                 { W = Wv; bias = bv; }

    const int ty = tid >> 4;       // 0..15 (row group)
    const int tx = tid & 15;       // 0..15 (col group)

    const int lrow = tid >> 3;     // 0..31
    const int lf4  = (tid & 7) * 4;

    float acc[4][4] = {};

    for (int k0 = 0; k0 < DIM; k0 += BK) {
        // --- load A tile (64 tokens x 32 d), store transposed ---
        #pragma unroll
        for (int r = 0; r < 2; r++) {
            const int row = lrow + r * 32;  // token within tile
            const float4 v = *(const float4*)&x[(size_t)(t0 + row) * ND + n * DIM + k0 + lf4];
            As[lf4 + 0][row] = v.x;
            As[lf4 + 1][row] = v.y;
            As[lf4 + 2][row] = v.z;
            As[lf4 + 3][row] = v.w;
        }
        // --- load B tile (32 d x 64 cols) ---
        {
            const int d = k0 + lrow;
            #pragma unroll
            for (int r = 0; r < 2; r++) {
                const int cc = c0 + lf4 + r * 32;
                const int h = cc >> 5;
                const int f = cc & 31;
                float4 v;
                if (which == 0)
                    v = *(const float4*)&W[(((size_t)h * NJ + n) * DIM + d) * FD + f];
                else
                    v = *(const float4*)&W[((size_t)h * DIM + d) * FD + f];
                *(float4*)&Bs[lrow][lf4 + r * 32] = v;
            }
        }
        __syncthreads();

        #pragma unroll
        for (int k = 0; k < BK; k++) {
            const float a0 = As[k][ty * 4 + 0];
            const float a1 = As[k][ty * 4 + 1];
            const float a2 = As[k][ty * 4 + 2];
            const float a3 = As[k][ty * 4 + 3];
            const float4 b = *(const float4*)&Bs[k][tx * 4];
            acc[0][0] += a0 * b.x; acc[0][1] += a0 * b.y; acc[0][2] += a0 * b.z; acc[0][3] += a0 * b.w;
            acc[1][0] += a1 * b.x; acc[1][1] += a1 * b.y; acc[1][2] += a1 * b.z; acc[1][3] += a1 * b.w;
            acc[2][0] += a2 * b.x; acc[2][1] += a2 * b.y; acc[2][2] += a2 * b.z; acc[2][3] += a2 * b.w;
            acc[3][0] += a3 * b.x; acc[3][1] += a3 * b.y; acc[3][2] += a3 * b.z; acc[3][3] += a3 * b.w;
        }
        __syncthreads();
    }

    float* outp = (which == 0) ? g_Q : (which == 1) ? g_K : g_V;
    #pragma unroll
    for (int j = 0; j < 4; j++) {
        const int c = c0 + tx * 4 + j;
        const int h = c >> 5;
        const int f = c & 31;
        const float bb = (which == 0) ? bias[((size_t)h * NJ + n) * FD + f]
                                      : bias[h * FD + f];
        #pragma unroll
        for (int i = 0; i < 4; i++) {
            const int t = t0 + ty * 4 + i;
            outp[(((size_t)t * NH + h) * NJ + n) * FD + f] = acc[i][j] + bb;
        }
    }
}

// ---------------------------------------------------------------------------
// Kernel 2: attention (per token, warp-per-head) + residual + LayerNorm.
// Lane n (< 24) owns q-row n in registers; k/v read via broadcast LDS.128.
// Attention output assembled in smem as [n][h*32+f] = token row layout,
// then residual + LN + affine, written straight to d_out.
// ---------------------------------------------------------------------------
__global__ __launch_bounds__(256)
void attn_ln(const float* __restrict__ x,
             const float* __restrict__ gamma, const float* __restrict__ beta,
             float* __restrict__ outg)
{
    extern __shared__ float sm[];
    float* qs  = sm;                    // [8][768]
    float* ks  = qs + NH * NJ * FD;     // [8][768]
    float* vs  = ks + NH * NJ * FD;     // [8][768]
    float* ob  = vs + NH * NJ * FD;     // [6144] token row
    float* red = ob + ND;               // reductions

    const int t    = blockIdx.x;
    const int tid  = threadIdx.x;
    const int w    = tid >> 5;   // head
    const int lane = tid & 31;

    const size_t base = ((size_t)t * NH + w) * (NJ * FD);
    for (int i = lane; i < NJ * FD; i += 32) {
        qs[w * 768 + i] = g_Q[base + i];
        ks[w * 768 + i] = g_K[base + i];
        vs[w * 768 + i] = g_V[base + i];
    }
    __syncwarp();

    if (lane < NJ) {
        const int n = lane;
        float q[FD];
        #pragma unroll
        for (int f = 0; f < FD; f++) q[f] = qs[w * 768 + n * FD + f];

        float s[NJ];
        float mx = -1e30f;
        #pragma unroll
        for (int m = 0; m < NJ; m++) {
            float a = 0.f;
            #pragma unroll
            for (int f4 = 0; f4 < FD; f4 += 4) {
                const float4 kv = *(const float4*)&ks[w * 768 + m * FD + f4];
                a += q[f4 + 0] * kv.x + q[f4 + 1] * kv.y
                   + q[f4 + 2] * kv.z + q[f4 + 3] * kv.w;
            }
            s[m] = a * 0.17677669529663687f;   // 1/sqrt(32)
            mx = fmaxf(mx, s[m]);
        }
        float sum = 0.f;
        #pragma unroll
        for (int m = 0; m < NJ; m++) { s[m] = __expf(s[m] - mx); sum += s[m]; }
        const float inv = 1.0f / sum;
        #pragma unroll
        for (int m = 0; m < NJ; m++) s[m] *= inv;

        #pragma unroll
        for (int f4 = 0; f4 < FD; f4 += 4) {
            float4 o = make_float4(0.f, 0.f, 0.f, 0.f);
            #pragma unroll
            for (int m = 0; m < NJ; m++) {
                const float4 vv = *(const float4*)&vs[w * 768 + m * FD + f4];
                o.x += s[m] * vv.x; o.y += s[m] * vv.y;
                o.z += s[m] * vv.z; o.w += s[m] * vv.w;
            }
            *(float4*)&ob[n * HF + w * FD + f4] = o;
        }
    }
    __syncthreads();

    // residual + LayerNorm over ND
    float lsum = 0.f, lsq = 0.f;
    const float* xr = x + (size_t)t * ND;
    for (int i = tid; i < ND; i += 256) {
        const float y = xr[i] + ob[i];
        ob[i] = y;
        lsum += y;
        lsq  += y * y;
    }
    #pragma unroll
    for (int o = 16; o > 0; o >>= 1) {
        lsum += __shfl_xor_sync(0xFFFFFFFFu, lsum, o);
        lsq  += __shfl_xor_sync(0xFFFFFFFFu, lsq,  o);
    }
    if (lane == 0) { red[w] = lsum; red[8 + w] = lsq; }
    __syncthreads();
    if (tid == 0) {
        float a = 0.f, b = 0.f;
        #pragma unroll
        for (int i = 0; i < 8; i++) { a += red[i]; b += red[8 + i]; }
        const float mu  = a / (float)ND;
        const float var = b / (float)ND - mu * mu;
        red[16] = mu;
        red[17] = rsqrtf(var + 1e-5f);
    }
    __syncthreads();
    const float mu = red[16], rstd = red[17];
    float* orow = outg + (size_t)t * ND;
    for (int i = tid; i < ND; i += 256) {
        orow[i] = (ob[i] - mu) * rstd * gamma[i] + beta[i];
    }
}

// ---------------------------------------------------------------------------
extern "C" void kernel_launch(void* const* d_in, const int* in_sizes, int n_in,
                              void* d_out, int out_size)
{
    const float* x     = (const float*)d_in[0];
    const float* Wq    = (const float*)d_in[1];
    const float* bq    = (const float*)d_in[2];
    const float* Wk    = (const float*)d_in[3];
    const float* bk    = (const float*)d_in[4];
    const float* Wv    = (const float*)d_in[5];
    const float* bv    = (const float*)d_in[6];
    const float* gamma = (const float*)d_in[7];
    const float* beta  = (const float*)d_in[8];
    float* out = (float*)d_out;

    dim3 grid1(T_TOK / BM, HF / BN, NJ * 3);
    qkv_gemm<<<grid1, 256>>>(x, Wq, bq, Wk, bk, Wv, bv);

    const int smem = (3 * NH * NJ * FD + ND + 64) * (int)sizeof(float);  // 98,560 B
    cudaFuncSetAttribute(attn_ln, cudaFuncAttributeMaxDynamicSharedMemorySize, smem);
    attn_ln<<<T_TOK, 256, smem>>>(x, gamma, beta, out);
}

// round 3
// speedup vs baseline: 3.2314x; 3.2314x over previous
#include <cuda_runtime.h>
#include <cuda_bf16.h>
#include <cstdint>

// ---------------------------------------------------------------------------
// Problem constants
// ---------------------------------------------------------------------------
#define T_TOK 8192
#define NJ    24
#define DIM   256
#define NH    8
#define FD    32
#define ND    6144                 // NJ*DIM
#define ROWS_KV (T_TOK * NJ)       // 196608

// Scratch (bf16): Q/K/V in [t][h][n][f] layout; pre-transposed weights K-major.
__device__ __nv_bfloat16 g_Q[(size_t)T_TOK * NH * NJ * FD];
__device__ __nv_bfloat16 g_K[(size_t)T_TOK * NH * NJ * FD];
__device__ __nv_bfloat16 g_V[(size_t)T_TOK * NH * NJ * FD];
__device__ __nv_bfloat16 g_WqT[(size_t)NJ * 256 * 256];  // [n][c][d]
__device__ __nv_bfloat16 g_WkT[256 * 256];               // [c][d]
__device__ __nv_bfloat16 g_WvT[256 * 256];

__device__ __forceinline__ uint32_t smem_u32(const void* p) {
    uint32_t a;
    asm("{ .reg .u64 t; cvta.to.shared.u64 t, %1; cvt.u32.u64 %0, t; }" : "=r"(a) : "l"(p));
    return a;
}

__device__ __forceinline__ void ldmatrix_x4(uint32_t* r, uint32_t addr) {
    asm volatile("ldmatrix.sync.aligned.m8n8.x4.shared.b16 {%0,%1,%2,%3}, [%4];"
                 : "=r"(r[0]), "=r"(r[1]), "=r"(r[2]), "=r"(r[3]) : "r"(addr));
}

__device__ __forceinline__ void mma_bf16(float* c, const uint32_t* a, const uint32_t* b) {
    asm volatile("mma.sync.aligned.m16n8k16.row.col.f32.bf16.bf16.f32 "
                 "{%0,%1,%2,%3}, {%4,%5,%6,%7}, {%8,%9}, {%0,%1,%2,%3};"
                 : "+f"(c[0]), "+f"(c[1]), "+f"(c[2]), "+f"(c[3])
                 : "r"(a[0]), "r"(a[1]), "r"(a[2]), "r"(a[3]), "r"(b[0]), "r"(b[1]));
}

// ---------------------------------------------------------------------------
// Prep: transpose + convert weights to K-major bf16.
// ---------------------------------------------------------------------------
__global__ void prep_w(const float* __restrict__ Wq, const float* __restrict__ Wk,
                       const float* __restrict__ Wv) {
    const int NQ = NJ * 65536;
    int i = blockIdx.x * 256 + threadIdx.x;
    if (i < NQ) {
        int n = i >> 16, rem = i & 65535, c = rem >> 8, d = rem & 255;
        int h = c >> 5, f = c & 31;
        g_WqT[i] = __float2bfloat16(Wq[(((size_t)(h * NJ + n) * 256) + d) * 32 + f]);
    } else if (i < NQ + 65536) {
        int j = i - NQ, c = j >> 8, d = j & 255, h = c >> 5, f = c & 31;
        g_WkT[j] = __float2bfloat16(Wk[((size_t)(h * 256 + d)) * 32 + f]);
    } else if (i < NQ + 131072) {
        int j = i - NQ - 65536, c = j >> 8, d = j & 255, h = c >> 5, f = c & 31;
        g_WvT[j] = __float2bfloat16(Wv[((size_t)(h * 256 + d)) * 32 + f]);
    }
}

// ---------------------------------------------------------------------------
// QKV GEMM via mma.sync bf16 (m16n8k16). CTA tile 128x128, BK=32, 8 warps
// of 32x64. KV=1: A = flat x (196608x256); z=0 -> K, z=1 -> V.
// KV=0: A = x[:, n*256:+256] (8192x256) for joint n = blockIdx.z.
// ---------------------------------------------------------------------------
#define ASTRIDE 40   // 32 k + 8 pad (bf16 elems); 80B row stride

template <int KV>
__global__ __launch_bounds__(256)
void qkv_gemm(const float* __restrict__ x,
              const float* __restrict__ bq, const float* __restrict__ bk,
              const float* __restrict__ bv) {
    __shared__ __nv_bfloat16 As[128 * ASTRIDE];
    __shared__ __nv_bfloat16 Bs[128 * ASTRIDE];
    __shared__ float sbias[128];

    const int tid  = threadIdx.x;
    const int lane = tid & 31;
    const int wid  = tid >> 5;
    const int wm   = (wid & 3) * 32;    // warp m offset
    const int wn   = (wid >> 2) * 64;   // warp n offset

    const size_t row0 = (size_t)blockIdx.x * 128;
    const int    c0   = blockIdx.y * 128;

    const __nv_bfloat16* WT;
    __nv_bfloat16* dst;
    if (KV) {
        if (blockIdx.z == 0) { WT = g_WkT; dst = g_K; }
        else                 { WT = g_WvT; dst = g_V; }
    } else {
        WT = g_WqT + (size_t)blockIdx.z * 65536;
        dst = g_Q;
    }

    if (tid < 128) {
        const int c = c0 + tid, h = c >> 5, f = c & 31;
        if (KV) sbias[tid] = (blockIdx.z == 0) ? bk[c] : bv[c];
        else    sbias[tid] = bq[((h * NJ + blockIdx.z) * FD) + f];
    }

    // global load slots
    const int arow = tid >> 1, aseg = (tid & 1) * 16;   // A: 16 floats each
    const float* aptr = KV ? (x + (row0 + arow) * 256 + aseg)
                           : (x + (row0 + arow) * (size_t)ND + (size_t)blockIdx.z * DIM + aseg);
    const __nv_bfloat16* bptr = WT + (size_t)(c0 + arow) * 256 + aseg;

    float4 aReg[4];
    uint4  bReg[2];

    #pragma unroll
    for (int q = 0; q < 4; q++) aReg[q] = ((const float4*)aptr)[q];
    bReg[0] = ((const uint4*)bptr)[0];
    bReg[1] = ((const uint4*)bptr)[1];

    float acc[2][8][4] = {};

    const uint32_t as_base = smem_u32(As);
    const uint32_t bs_base = smem_u32(Bs);

    // ldmatrix lane address components
    const int lmat = lane >> 3, lr = lane & 7;

    #pragma unroll 1
    for (int s = 0; s < 8; s++) {
        __syncthreads();
        // store staged regs -> smem (bf16)
        #pragma unroll
        for (int q = 0; q < 4; q++) {
            __nv_bfloat162 p0 = __float22bfloat162_rn(make_float2(aReg[q].x, aReg[q].y));
            __nv_bfloat162 p1 = __float22bfloat162_rn(make_float2(aReg[q].z, aReg[q].w));
            uint2 w; w.x = *(uint32_t*)&p0; w.y = *(uint32_t*)&p1;
            *(uint2*)&As[arow * ASTRIDE + aseg + q * 4] = w;
        }
        *(uint4*)&Bs[arow * ASTRIDE + aseg + 0] = bReg[0];
        *(uint4*)&Bs[arow * ASTRIDE + aseg + 8] = bReg[1];
        __syncthreads();

        if (s < 7) {
            const int k0 = (s + 1) * 32;
            #pragma unroll
            for (int q = 0; q < 4; q++) aReg[q] = ((const float4*)(aptr + k0))[q];
            bReg[0] = ((const uint4*)(bptr + k0))[0];
            bReg[1] = ((const uint4*)(bptr + k0))[1];
        }

        #pragma unroll
        for (int kh = 0; kh < 2; kh++) {
            uint32_t af[2][4], bf[4][4];
            #pragma unroll
            for (int i = 0; i < 2; i++) {
                const int row = wm + i * 16 + (lmat & 1) * 8 + lr;
                const int col = kh * 16 + (lmat >> 1) * 8;
                ldmatrix_x4(af[i], as_base + (row * ASTRIDE + col) * 2);
            }
            #pragma unroll
            for (int j = 0; j < 4; j++) {
                const int row = wn + j * 16 + (lmat >> 1) * 8 + lr;
                const int col = kh * 16 + (lmat & 1) * 8;
                ldmatrix_x4(bf[j], bs_base + (row * ASTRIDE + col) * 2);
            }
            #pragma unroll
            for (int i = 0; i < 2; i++)
                #pragma unroll
                for (int jj = 0; jj < 8; jj++)
                    mma_bf16(acc[i][jj], af[i], &bf[jj >> 1][(jj & 1) * 2]);
        }
    }

    // epilogue: bias add, fp32->bf16, scatter to [t][h][n][f]
    #pragma unroll
    for (int i = 0; i < 2; i++) {
        #pragma unroll
        for (int jj = 0; jj < 8; jj++) {
            const int cl = wn + jj * 8 + (lane & 3) * 2;   // local col (even)
            const int c  = c0 + cl;
            const int h = c >> 5, f = c & 31;
            const float b0 = sbias[cl], b1 = sbias[cl + 1];
            #pragma unroll
            for (int half = 0; half < 2; half++) {
                const size_t r = row0 + wm + i * 16 + (lane >> 2) + half * 8;
                int t, n;
                if (KV) { t = (int)(r / 24); n = (int)(r - (size_t)t * 24); }
                else    { t = (int)r; n = blockIdx.z; }
                __nv_bfloat162 pk = __float22bfloat162_rn(
                    make_float2(acc[i][jj][half * 2] + b0, acc[i][jj][half * 2 + 1] + b1));
                *(__nv_bfloat162*)(dst + (((size_t)t * NH + h) * NJ + n) * FD + f) = pk;
            }
        }
    }
}

// ---------------------------------------------------------------------------
// Attention + residual + LayerNorm. 192 threads = (h, n) pairs per token.
// ---------------------------------------------------------------------------
__device__ __forceinline__ void bf8_to_f(uint4 w, float* out) {
    *(float2*)(out + 0) = __bfloat1622float2(*(__nv_bfloat162*)&w.x);
    *(float2*)(out + 2) = __bfloat1622float2(*(__nv_bfloat162*)&w.y);
    *(float2*)(out + 4) = __bfloat1622float2(*(__nv_bfloat162*)&w.z);
    *(float2*)(out + 6) = __bfloat1622float2(*(__nv_bfloat162*)&w.w);
}

__global__ __launch_bounds__(192)
void attn_ln(const float* __restrict__ x, const float* __restrict__ gamma,
             const float* __restrict__ beta, float* __restrict__ outg) {
    extern __shared__ float sm[];
    float* ksh = sm;            // [8][24][32] fp32 (reused as ob)
    float* vsh = sm + ND;
    float* red = sm + 2 * ND;

    const int t = blockIdx.x;
    const int tid = threadIdx.x;
    const int h = tid / 24, n = tid - h * 24;
    const int w = tid >> 5, lane = tid & 31;

    const __nv_bfloat16* kb = g_K + (size_t)t * ND;
    const __nv_bfloat16* vb = g_V + (size_t)t * ND;
    #pragma unroll
    for (int p = 0; p < 4; p++) {
        const int i = tid + p * 192;
        float tmp[8];
        bf8_to_f(*(const uint4*)(kb + i * 8), tmp);
        ((float4*)(ksh + i * 8))[0] = *(float4*)tmp;
        ((float4*)(ksh + i * 8))[1] = *(float4*)(tmp + 4);
        bf8_to_f(*(const uint4*)(vb + i * 8), tmp);
        ((float4*)(vsh + i * 8))[0] = *(float4*)tmp;
        ((float4*)(vsh + i * 8))[1] = *(float4*)(tmp + 4);
    }
    float q[FD];
    {
        const uint4* qp = (const uint4*)(g_Q + (size_t)t * ND + (h * NJ + n) * FD);
        #pragma unroll
        for (int j = 0; j < 4; j++) bf8_to_f(qp[j], q + j * 8);
    }
    __syncthreads();

    float s[NJ];
    float mx = -1e30f;
    #pragma unroll
    for (int m = 0; m < NJ; m++) {
        const float4* kr = (const float4*)(ksh + (h * NJ + m) * FD);
        float a = 0.f;
        #pragma unroll
        for (int j = 0; j < 8; j++) {
            const float4 kv = kr[j];
            a += q[4 * j + 0] * kv.x + q[4 * j + 1] * kv.y
               + q[4 * j + 2] * kv.z + q[4 * j + 3] * kv.w;
        }
        s[m] = a * 0.17677669529663687f;
        mx = fmaxf(mx, s[m]);
    }
    float sum = 0.f;
    #pragma unroll
    for (int m = 0; m < NJ; m++) { s[m] = __expf(s[m] - mx); sum += s[m]; }
    const float inv = 1.0f / sum;
    #pragma unroll
    for (int m = 0; m < NJ; m++) s[m] *= inv;

    __syncthreads();   // ksh reads done -> reuse as ob

    float o[FD] = {};
    #pragma unroll
    for (int m = 0; m < NJ; m++) {
        const float4* vr = (const float4*)(vsh + (h * NJ + m) * FD);
        const float sv = s[m];
        #pragma unroll
        for (int j = 0; j < 8; j++) {
            const float4 vv = vr[j];
            o[4 * j + 0] += sv * vv.x; o[4 * j + 1] += sv * vv.y;
            o[4 * j + 2] += sv * vv.z; o[4 * j + 3] += sv * vv.w;
        }
    }
    {
        float4* op = (float4*)(ksh + n * (NH * FD) + h * FD);
        #pragma unroll
        for (int j = 0; j < 8; j++)
            op[j] = make_float4(o[4 * j], o[4 * j + 1], o[4 * j + 2], o[4 * j + 3]);
    }
    __syncthreads();

    float lsum = 0.f, lsq = 0.f;
    const float4* xr = (const float4*)(x + (size_t)t * ND);
    float4* ob = (float4*)ksh;
    #pragma unroll
    for (int p = 0; p < 8; p++) {
        const int i = tid + p * 192;
        float4 y = xr[i];
        const float4 a = ob[i];
        y.x += a.x; y.y += a.y; y.z += a.z; y.w += a.w;
        ob[i] = y;
        lsum += y.x + y.y + y.z + y.w;
        lsq  += y.x * y.x + y.y * y.y + y.z * y.z + y.w * y.w;
    }
    #pragma unroll
    for (int off = 16; off > 0; off >>= 1) {
        lsum += __shfl_xor_sync(0xFFFFFFFFu, lsum, off);
        lsq  += __shfl_xor_sync(0xFFFFFFFFu, lsq,  off);
    }
    if (lane == 0) { red[w] = lsum; red[8 + w] = lsq; }
    __syncthreads();
    if (tid == 0) {
        float a = 0.f, b = 0.f;
        #pragma unroll
        for (int i = 0; i < 6; i++) { a += red[i]; b += red[8 + i]; }
        const float mu = a / (float)ND;
        const float var = b / (float)ND - mu * mu;
        red[16] = mu;
        red[17] = rsqrtf(var + 1e-5f);
    }
    __syncthreads();
    const float mu = red[16], rstd = red[17];
    const float4* g4 = (const float4*)gamma;
    const float4* b4 = (const float4*)beta;
    float4* orow = (float4*)(outg + (size_t)t * ND);
    #pragma unroll
    for (int p = 0; p < 8; p++) {
        const int i = tid + p * 192;
        const float4 y = ob[i], gg = g4[i], bb = b4[i];
        orow[i] = make_float4((y.x - mu) * rstd * gg.x + bb.x,
                              (y.y - mu) * rstd * gg.y + bb.y,
                              (y.z - mu) * rstd * gg.z + bb.z,
                              (y.w - mu) * rstd * gg.w + bb.w);
    }
}

// ---------------------------------------------------------------------------
extern "C" void kernel_launch(void* const* d_in, const int* in_sizes, int n_in,
                              void* d_out, int out_size) {
    const float* x     = (const float*)d_in[0];
    const float* Wq    = (const float*)d_in[1];
    const float* bq    = (const float*)d_in[2];
    const float* Wk    = (const float*)d_in[3];
    const float* bk    = (const float*)d_in[4];
    const float* Wv    = (const float*)d_in[5];
    const float* bv    = (const float*)d_in[6];
    const float* gamma = (const float*)d_in[7];
    const float* beta  = (const float*)d_in[8];
    float* out = (float*)d_out;

    prep_w<<<6656, 256>>>(Wq, Wk, Wv);

    qkv_gemm<1><<<dim3(ROWS_KV / 128, 2, 2),  256>>>(x, bq, bk, bv);
    qkv_gemm<0><<<dim3(T_TOK / 128, 2, NJ),  256>>>(x, bq, bk, bv);

    const int SMEM_ATTN = (2 * ND + 32) * (int)sizeof(float);  // 49280
    cudaFuncSetAttribute(attn_ln, cudaFuncAttributeMaxDynamicSharedMemorySize, SMEM_ATTN);
    attn_ln<<<T_TOK, 192, SMEM_ATTN>>>(x, gamma, beta, out);
}

// round 4
// speedup vs baseline: 3.6490x; 1.1292x over previous
#include <cuda_runtime.h>
#include <cuda_bf16.h>
#include <cstdint>

// ---------------------------------------------------------------------------
// Problem constants
// ---------------------------------------------------------------------------
#define T_TOK 8192
#define NJ    24
#define DIM   256
#define NH    8
#define FD    32
#define ND    6144                 // NJ*DIM

// Scratch (bf16): Q/K/V in [t][h][n][f] layout; pre-transposed weights K-major.
__device__ __nv_bfloat16 g_Q[(size_t)T_TOK * NH * NJ * FD];
__device__ __nv_bfloat16 g_K[(size_t)T_TOK * NH * NJ * FD];
__device__ __nv_bfloat16 g_V[(size_t)T_TOK * NH * NJ * FD];
__device__ __nv_bfloat16 g_WqT[(size_t)NJ * 256 * 256];  // [n][c][d]
__device__ __nv_bfloat16 g_WkT[256 * 256];               // [c][d]
__device__ __nv_bfloat16 g_WvT[256 * 256];

__device__ __forceinline__ uint32_t smem_u32(const void* p) {
    uint32_t a;
    asm("{ .reg .u64 t; cvta.to.shared.u64 t, %1; cvt.u32.u64 %0, t; }" : "=r"(a) : "l"(p));
    return a;
}

__device__ __forceinline__ void ldmatrix_x4(uint32_t* r, uint32_t addr) {
    asm volatile("ldmatrix.sync.aligned.m8n8.x4.shared.b16 {%0,%1,%2,%3}, [%4];"
                 : "=r"(r[0]), "=r"(r[1]), "=r"(r[2]), "=r"(r[3]) : "r"(addr));
}

__device__ __forceinline__ void mma_bf16(float* c, const uint32_t* a, const uint32_t* b) {
    asm volatile("mma.sync.aligned.m16n8k16.row.col.f32.bf16.bf16.f32 "
                 "{%0,%1,%2,%3}, {%4,%5,%6,%7}, {%8,%9}, {%0,%1,%2,%3};"
                 : "+f"(c[0]), "+f"(c[1]), "+f"(c[2]), "+f"(c[3])
                 : "r"(a[0]), "r"(a[1]), "r"(a[2]), "r"(a[3]), "r"(b[0]), "r"(b[1]));
}

// ---------------------------------------------------------------------------
// Prep: transpose + convert weights to K-major bf16.
// ---------------------------------------------------------------------------
__global__ void prep_w(const float* __restrict__ Wq, const float* __restrict__ Wk,
                       const float* __restrict__ Wv) {
    const int NQ = NJ * 65536;
    int i = blockIdx.x * 256 + threadIdx.x;
    if (i < NQ) {
        int n = i >> 16, rem = i & 65535, c = rem >> 8, d = rem & 255;
        int h = c >> 5, f = c & 31;
        g_WqT[i] = __float2bfloat16(Wq[(((size_t)(h * NJ + n) * 256) + d) * 32 + f]);
    } else if (i < NQ + 65536) {
        int j = i - NQ, c = j >> 8, d = j & 255, h = c >> 5, f = c & 31;
        g_WkT[j] = __float2bfloat16(Wk[((size_t)(h * 256 + d)) * 32 + f]);
    } else if (i < NQ + 131072) {
        int j = i - NQ - 65536, c = j >> 8, d = j & 255, h = c >> 5, f = c & 31;
        g_WvT[j] = __float2bfloat16(Wv[((size_t)(h * 256 + d)) * 32 + f]);
    }
}

// ---------------------------------------------------------------------------
// Fused QKV GEMM. CTA = (128 tokens, joint n). A tile (128x256 bf16) loaded
// ONCE into resident smem; 6 sections (Q/K/V x 2 column halves of 128) each
// stream B (128 x 32k chunks) and run mma.sync m16n8k16.
// x is read exactly once across the whole launch.
// ---------------------------------------------------------------------------
#define ASTR_A 264   // 256 + 8 pad (bf16)
#define ASTR_B 40    // 32 + 8 pad

__global__ __launch_bounds__(256, 2)
void fused_qkv(const float* __restrict__ x,
               const float* __restrict__ bq, const float* __restrict__ bk,
               const float* __restrict__ bv) {
    extern __shared__ char smem[];
    __nv_bfloat16* As = (__nv_bfloat16*)smem;                     // 128*264*2 = 67584
    __nv_bfloat16* Bs = (__nv_bfloat16*)(smem + 67584);           // 128*40*2  = 10240
    float* sbias      = (float*)(smem + 67584 + 10240);           // 768 floats

    const int tid  = threadIdx.x;
    const int lane = tid & 31;
    const int wid  = tid >> 5;
    const int wm   = (wid & 3) * 32;    // warp m offset
    const int wn   = (wid >> 2) * 64;   // warp n offset (within 128-col section)

    const int n    = blockIdx.y;        // joint
    const size_t row0 = (size_t)blockIdx.x * 128;

    // biases: [0..255]=Q(n), [256..511]=K, [512..767]=V; col c = h*32+f
    {
        const int c = tid, h = c >> 5, f = c & 31;
        sbias[c]       = bq[(h * NJ + n) * FD + f];
        sbias[256 + c] = bk[c];
        sbias[512 + c] = bv[c];
    }

    // ---- load A tile: x[row0..+128, n*256..+256] fp32 -> bf16 smem ----
    {
        const float* ab = x + row0 * (size_t)ND + (size_t)n * DIM;
        #pragma unroll
        for (int p = 0; p < 32; p++) {
            const int flat = tid + p * 256;      // float4 index, 8192 total
            const int row  = flat >> 6;          // 64 float4 per row
            const int col  = (flat & 63) * 4;
            const float4 v = *(const float4*)(ab + (size_t)row * ND + col);
            __nv_bfloat162 p0 = __float22bfloat162_rn(make_float2(v.x, v.y));
            __nv_bfloat162 p1 = __float22bfloat162_rn(make_float2(v.z, v.w));
            uint2 w; w.x = *(uint32_t*)&p0; w.y = *(uint32_t*)&p1;
            *(uint2*)&As[row * ASTR_A + col] = w;
        }
    }
    __syncthreads();

    const __nv_bfloat16* WTs[3] = { g_WqT + (size_t)n * 65536, g_WkT, g_WvT };
    __nv_bfloat16* dsts[3] = { g_Q, g_K, g_V };

    const uint32_t as_base = smem_u32(As);
    const uint32_t bs_base = smem_u32(Bs);
    const int lmat = lane >> 3, lr = lane & 7;

    // B global-load slot
    const int bRow = tid >> 1, bSeg = (tid & 1) * 16;

    float acc[2][8][4] = {};
    uint4 bReg[2];
    {
        const __nv_bfloat16* bp = WTs[0] + (size_t)bRow * 256 + bSeg;
        bReg[0] = ((const uint4*)bp)[0];
        bReg[1] = ((const uint4*)bp)[1];
    }

    #pragma unroll 1
    for (int sc = 0; sc < 48; sc++) {
        const int sec   = sc >> 3;
        const int chunk = sc & 7;
        const int which = sec >> 1;
        const int c0    = (sec & 1) * 128;

        __syncthreads();
        *(uint4*)&Bs[bRow * ASTR_B + bSeg + 0] = bReg[0];
        *(uint4*)&Bs[bRow * ASTR_B + bSeg + 8] = bReg[1];
        __syncthreads();

        if (sc < 47) {
            const int nsc = sc + 1;
            const int nsec = nsc >> 3, nch = nsc & 7;
            const __nv_bfloat16* bp = WTs[nsec >> 1]
                + (size_t)((nsec & 1) * 128 + bRow) * 256 + nch * 32 + bSeg;
            bReg[0] = ((const uint4*)bp)[0];
            bReg[1] = ((const uint4*)bp)[1];
        }

        #pragma unroll
        for (int kh = 0; kh < 2; kh++) {
            uint32_t af[2][4], bf[4][4];
            #pragma unroll
            for (int i = 0; i < 2; i++) {
                const int row = wm + i * 16 + (lmat & 1) * 8 + lr;
                const int col = chunk * 32 + kh * 16 + (lmat >> 1) * 8;
                ldmatrix_x4(af[i], as_base + (row * ASTR_A + col) * 2);
            }
            #pragma unroll
            for (int j = 0; j < 4; j++) {
                const int row = wn + j * 16 + (lmat >> 1) * 8 + lr;
                const int col = kh * 16 + (lmat & 1) * 8;
                ldmatrix_x4(bf[j], bs_base + (row * ASTR_B + col) * 2);
            }
            #pragma unroll
            for (int i = 0; i < 2; i++)
                #pragma unroll
                for (int jj = 0; jj < 8; jj++)
                    mma_bf16(acc[i][jj], af[i], &bf[jj >> 1][(jj & 1) * 2]);
        }

        if (chunk == 7) {
            // epilogue for this section
            __nv_bfloat16* dst = dsts[which];
            #pragma unroll
            for (int i = 0; i < 2; i++) {
                #pragma unroll
                for (int jj = 0; jj < 8; jj++) {
                    const int cl = wn + jj * 8 + (lane & 3) * 2;
                    const int c  = c0 + cl;                    // 0..255
                    const int h = c >> 5, f = c & 31;
                    const float b0 = sbias[which * 256 + c];
                    const float b1 = sbias[which * 256 + c + 1];
                    #pragma unroll
                    for (int half = 0; half < 2; half++) {
                        const size_t t = row0 + wm + i * 16 + (lane >> 2) + half * 8;
                        __nv_bfloat162 pk = __float22bfloat162_rn(
                            make_float2(acc[i][jj][half * 2] + b0,
                                        acc[i][jj][half * 2 + 1] + b1));
                        *(__nv_bfloat162*)(dst + (((t * NH + h) * NJ + n) * FD) + f) = pk;
                        acc[i][jj][half * 2] = 0.f;
                        acc[i][jj][half * 2 + 1] = 0.f;
                    }
                }
            }
        }
    }
}

// ---------------------------------------------------------------------------
// Attention + residual + LayerNorm. 192 threads = (h, n) pairs per token.
// K/V staged as raw bf16 (halved LDS/STS traffic); convert inline.
// ---------------------------------------------------------------------------
__global__ __launch_bounds__(192)
void attn_ln(const float* __restrict__ x, const float* __restrict__ gamma,
             const float* __restrict__ beta, float* __restrict__ outg) {
    extern __shared__ float sm[];
    float* ob = sm;                                       // 6144 fp32
    __nv_bfloat16* ksh = (__nv_bfloat16*)(sm + ND);       // 6144 bf16
    __nv_bfloat16* vsh = ksh + ND;                        // 6144 bf16
    float* red = (float*)(vsh + ND);

    const int t = blockIdx.x;
    const int tid = threadIdx.x;
    const int h = tid / 24, n = tid - h * 24;
    const int w = tid >> 5, lane = tid & 31;

    // stage K/V as raw bf16 (uint4 copies)
    const uint4* kb = (const uint4*)(g_K + (size_t)t * ND);
    const uint4* vb = (const uint4*)(g_V + (size_t)t * ND);
    uint4* k4 = (uint4*)ksh;
    uint4* v4 = (uint4*)vsh;
    #pragma unroll
    for (int p = 0; p < 4; p++) {
        const int i = tid + p * 192;      // 768 chunks of 8 bf16
        k4[i] = kb[i];
        v4[i] = vb[i];
    }
    // own q row -> fp32 regs
    float q[FD];
    {
        const uint4* qp = (const uint4*)(g_Q + (size_t)t * ND + (h * NJ + n) * FD);
        #pragma unroll
        for (int j = 0; j < 4; j++) {
            const uint4 wv = qp[j];
            *(float2*)(q + j * 8 + 0) = __bfloat1622float2(*(__nv_bfloat162*)&wv.x);
            *(float2*)(q + j * 8 + 2) = __bfloat1622float2(*(__nv_bfloat162*)&wv.y);
            *(float2*)(q + j * 8 + 4) = __bfloat1622float2(*(__nv_bfloat162*)&wv.z);
            *(float2*)(q + j * 8 + 6) = __bfloat1622float2(*(__nv_bfloat162*)&wv.w);
        }
    }
    __syncthreads();

    // scores
    float s[NJ];
    float mx = -1e30f;
    #pragma unroll
    for (int m = 0; m < NJ; m++) {
        const uint4* kr = (const uint4*)(ksh + (h * NJ + m) * FD);
        float a = 0.f;
        #pragma unroll
        for (int j = 0; j < 4; j++) {
            const uint4 wv = kr[j];
            const float2 c0 = __bfloat1622float2(*(__nv_bfloat162*)&wv.x);
            const float2 c1 = __bfloat1622float2(*(__nv_bfloat162*)&wv.y);
            const float2 c2 = __bfloat1622float2(*(__nv_bfloat162*)&wv.z);
            const float2 c3 = __bfloat1622float2(*(__nv_bfloat162*)&wv.w);
            a += q[j*8+0]*c0.x + q[j*8+1]*c0.y + q[j*8+2]*c1.x + q[j*8+3]*c1.y
               + q[j*8+4]*c2.x + q[j*8+5]*c2.y + q[j*8+6]*c3.x + q[j*8+7]*c3.y;
        }
        s[m] = a * 0.17677669529663687f;
        mx = fmaxf(mx, s[m]);
    }
    float sum = 0.f;
    #pragma unroll
    for (int m = 0; m < NJ; m++) { s[m] = __expf(s[m] - mx); sum += s[m]; }
    const float inv = 1.0f / sum;
    #pragma unroll
    for (int m = 0; m < NJ; m++) s[m] *= inv;

    // PV -> o, write into ob at [n*256 + h*32]
    float o[FD] = {};
    #pragma unroll
    for (int m = 0; m < NJ; m++) {
        const uint4* vr = (const uint4*)(vsh + (h * NJ + m) * FD);
        const float sv = s[m];
        #pragma unroll
        for (int j = 0; j < 4; j++) {
            const uint4 wv = vr[j];
            const float2 c0 = __bfloat1622float2(*(__nv_bfloat162*)&wv.x);
            const float2 c1 = __bfloat1622float2(*(__nv_bfloat162*)&wv.y);
            const float2 c2 = __bfloat1622float2(*(__nv_bfloat162*)&wv.z);
            const float2 c3 = __bfloat1622float2(*(__nv_bfloat162*)&wv.w);
            o[j*8+0] += sv*c0.x; o[j*8+1] += sv*c0.y;
            o[j*8+2] += sv*c1.x; o[j*8+3] += sv*c1.y;
            o[j*8+4] += sv*c2.x; o[j*8+5] += sv*c2.y;
            o[j*8+6] += sv*c3.x; o[j*8+7] += sv*c3.y;
        }
    }
    {
        float4* op = (float4*)(ob + n * (NH * FD) + h * FD);
        #pragma unroll
        for (int j = 0; j < 8; j++)
            op[j] = make_float4(o[4*j], o[4*j+1], o[4*j+2], o[4*j+3]);
    }
    __syncthreads();

    // residual + LN over 6144
    float lsum = 0.f, lsq = 0.f;
    const float4* xr = (const float4*)(x + (size_t)t * ND);
    float4* ob4 = (float4*)ob;
    #pragma unroll
    for (int p = 0; p < 8; p++) {
        const int i = tid + p * 192;
        float4 y = xr[i];
        const float4 a = ob4[i];
        y.x += a.x; y.y += a.y; y.z += a.z; y.w += a.w;
        ob4[i] = y;
        lsum += y.x + y.y + y.z + y.w;
        lsq  += y.x*y.x + y.y*y.y + y.z*y.z + y.w*y.w;
    }
    #pragma unroll
    for (int off = 16; off > 0; off >>= 1) {
        lsum += __shfl_xor_sync(0xFFFFFFFFu, lsum, off);
        lsq  += __shfl_xor_sync(0xFFFFFFFFu, lsq,  off);
    }
    if (lane == 0) { red[w] = lsum; red[8 + w] = lsq; }
    __syncthreads();
    if (tid == 0) {
        float a = 0.f, b = 0.f;
        #pragma unroll
        for (int i = 0; i < 6; i++) { a += red[i]; b += red[8 + i]; }
        const float mu = a / (float)ND;
        const float var = b / (float)ND - mu * mu;
        red[16] = mu;
        red[17] = rsqrtf(var + 1e-5f);
    }
    __syncthreads();
    const float mu = red[16], rstd = red[17];
    const float4* g4 = (const float4*)gamma;
    const float4* b4 = (const float4*)beta;
    float4* orow = (float4*)(outg + (size_t)t * ND);
    #pragma unroll
    for (int p = 0; p < 8; p++) {
        const int i = tid + p * 192;
        const float4 y = ob4[i], gg = g4[i], bb = b4[i];
        orow[i] = make_float4((y.x - mu) * rstd * gg.x + bb.x,
                              (y.y - mu) * rstd * gg.y + bb.y,
                              (y.z - mu) * rstd * gg.z + bb.z,
                              (y.w - mu) * rstd * gg.w + bb.w);
    }
}

// ---------------------------------------------------------------------------
extern "C" void kernel_launch(void* const* d_in, const int* in_sizes, int n_in,
                              void* d_out, int out_size) {
    const float* x     = (const float*)d_in[0];
    const float* Wq    = (const float*)d_in[1];
    const float* bq    = (const float*)d_in[2];
    const float* Wk    = (const float*)d_in[3];
    const float* bk    = (const float*)d_in[4];
    const float* Wv    = (const float*)d_in[5];
    const float* bv    = (const float*)d_in[6];
    const float* gamma = (const float*)d_in[7];
    const float* beta  = (const float*)d_in[8];
    float* out = (float*)d_out;

    prep_w<<<6656, 256>>>(Wq, Wk, Wv);

    const int SMEM_G = 67584 + 10240 + 768 * 4;   // 80896
    cudaFuncSetAttribute(fused_qkv, cudaFuncAttributeMaxDynamicSharedMemorySize, SMEM_G);
    fused_qkv<<<dim3(T_TOK / 128, NJ), 256, SMEM_G>>>(x, bq, bk, bv);

    const int SMEM_ATTN = ND * 4 + 2 * ND * 2 + 128;   // 49280
    cudaFuncSetAttribute(attn_ln, cudaFuncAttributeMaxDynamicSharedMemorySize, SMEM_ATTN);
    attn_ln<<<T_TOK, 192, SMEM_ATTN>>>(x, gamma, beta, out);
}